// round 11
// baseline (speedup 1.0000x reference)
#include <cuda_runtime.h>
#include <cuda_bf16.h>

#define IMG_W 1024
#define IMG_H 1024
#define NC_TOTAL 48
#define ROWS 8
#define NLOAD (ROWS + 2)
#define NWARP 8

// v9 = v7 (proven best: 10 front-batched row loads, 8-row tile, early store)
//      with ALL mid-loop global loads removed: warp-boundary halo pixels are
//      exchanged through a small smem table filled right after the load batch.
__global__ void __launch_bounds__(256, 3) normconv3x3_v9(
    const float* __restrict__ x,
    const float* __restrict__ wt,
    float* __restrict__ out)
{
    __shared__ float sL[NWARP][NLOAD];   // lane0's v.x per warp/row  (left edge of warp span)
    __shared__ float sR[NWARP][NLOAD];   // lane31's v.w per warp/row (right edge of warp span)

    const int lane = threadIdx.x & 31;
    const int warp = threadIdx.x >> 5;             // 0..7
    const int b = blockIdx.x;
    const int y0 = (b & 127) << 3;                 // 128 8-row tiles
    const int nc = b >> 7;                         // 0..47
    const int c = nc % 3;

    const float* base = x + ((size_t)nc << 20) + ((size_t)threadIdx.x << 2);

    // ---- Phase 1: 10 branch-free batched row loads (MLP=10) ----
    float4 v[NLOAD];
    if (y0 != 0 && y0 != IMG_H - ROWS) {
#pragma unroll
        for (int r = 0; r < NLOAD; r++)
            v[r] = *reinterpret_cast<const float4*>(base + (size_t)(y0 - 1 + r) * IMG_W);
    } else {
#pragma unroll
        for (int r = 0; r < NLOAD; r++) {
            const int rr = y0 - 1 + r;
            const int rc = min(IMG_H - 1, max(0, rr));
            v[r] = *reinterpret_cast<const float4*>(base + (size_t)rc * IMG_W);
            if (rr != rc) v[r] = make_float4(0.f, 0.f, 0.f, 0.f);
        }
    }

    // Publish warp-edge pixels for cross-warp halo (rows outside image already zero)
    if (lane == 0) {
#pragma unroll
        for (int r = 0; r < NLOAD; r++) sL[warp][r] = v[r].x;
    }
    if (lane == 31) {
#pragma unroll
        for (int r = 0; r < NLOAD; r++) sR[warp][r] = v[r].w;
    }

    // Weights while the stores/sync settle
    float w[9];
    float ws2 = 0.f;
#pragma unroll
    for (int k = 0; k < 9; k++) { w[k] = __ldg(&wt[c * 9 + k]); ws2 += w[k] * w[k]; }
    const float winv = rsqrtf(ws2);
#pragma unroll
    for (int k = 0; k < 9; k++) w[k] *= winv;

    __syncthreads();

    float num[ROWS][4], sq[ROWS][4];
    float* op = out + ((size_t)nc << 20) + (size_t)y0 * IMG_W + ((size_t)threadIdx.x << 2);

    // Halo for input row 0 (shuffle + smem cross-warp; image edges are zero)
    float h0c = __shfl_up_sync(0xffffffffu, v[0].w, 1);
    float h5c = __shfl_down_sync(0xffffffffu, v[0].x, 1);
    if (lane == 0)  h0c = (warp > 0)         ? sR[warp - 1][0] : 0.f;
    if (lane == 31) h5c = (warp < NWARP - 1) ? sL[warp + 1][0] : 0.f;

#pragma unroll
    for (int r = 0; r < NLOAD; r++) {
        // next row's halo pipelined ahead of this row's compute
        float h0n = 0.f, h5n = 0.f;
        if (r + 1 < NLOAD) {
            h0n = __shfl_up_sync(0xffffffffu, v[r + 1].w, 1);
            h5n = __shfl_down_sync(0xffffffffu, v[r + 1].x, 1);
            if (lane == 0)  h0n = (warp > 0)         ? sR[warp - 1][r + 1] : 0.f;
            if (lane == 31) h5n = (warp < NWARP - 1) ? sL[warp + 1][r + 1] : 0.f;
        }

        const float a[6] = { h0c, v[r].x, v[r].y, v[r].z, v[r].w, h5c };

        float p[6];
#pragma unroll
        for (int i = 0; i < 6; i++) p[i] = a[i] * a[i];
        const float u = p[1] + p[2];
        const float t = p[3] + p[4];
        const float s[4] = { p[0] + u, u + p[3], p[2] + t, t + p[5] };

#pragma unroll
        for (int o = 0; o < ROWS; o++) {
            const int k = r - o;                    // weight row for this (input,output) pair
            if (k == 0) {
#pragma unroll
                for (int j = 0; j < 4; j++) {
                    num[o][j] = fmaf(w[0], a[j], fmaf(w[1], a[j + 1], w[2] * a[j + 2]));
                    sq[o][j] = s[j];
                }
            } else if (k == 1 || k == 2) {
                const float w0 = w[k * 3 + 0], w1 = w[k * 3 + 1], w2 = w[k * 3 + 2];
#pragma unroll
                for (int j = 0; j < 4; j++) {
                    num[o][j] = fmaf(w0, a[j], fmaf(w1, a[j + 1], fmaf(w2, a[j + 2], num[o][j])));
                    sq[o][j] += s[j];
                }
            }
        }

        // output row (r-2) complete after consuming input row r
        if (r >= 2) {
            const int o = r - 2;
            float4 ov;
            ov.x = num[o][0] * rsqrtf(sq[o][0]);
            ov.y = num[o][1] * rsqrtf(sq[o][1]);
            ov.z = num[o][2] * rsqrtf(sq[o][2]);
            ov.w = num[o][3] * rsqrtf(sq[o][3]);
            *reinterpret_cast<float4*>(op + (size_t)o * IMG_W) = ov;
        }

        h0c = h0n; h5c = h5n;
    }
}

extern "C" void kernel_launch(void* const* d_in, const int* in_sizes, int n_in,
                              void* d_out, int out_size) {
    const float* x  = (const float*)d_in[0];
    const float* wt = (const float*)d_in[1];
    float* out = (float*)d_out;

    dim3 grid(NC_TOTAL * (IMG_H / ROWS));   // 6144 blocks, 256 threads = full row width
    normconv3x3_v9<<<grid, 256>>>(x, wt, out);
}

// round 12
// speedup vs baseline: 1.3045x; 1.3045x over previous
#include <cuda_runtime.h>
#include <cuda_bf16.h>

#define IMG_W 1024
#define IMG_H 1024
#define NC_TOTAL 48
#define TROWS 16            // output rows per CTA (two 8-row tiles)

// v10 = v7 (proven best structure) x2 tiles per CTA, software-pipelined:
//  - tile1: 10 front-batched row loads (rows y0-1..y0+8), v7 loop verbatim
//  - tile2: reuses vA[8],vA[9]; 8 new rows (vB) issued at tile1's r=9
//  - all row sources compile-time static (no dynamic cross-array select -> no spill)
//  - 18 loads / 16 output rows = 1.125x read amplification; grid halved
__global__ void __launch_bounds__(256, 3) normconv3x3_v10(
    const float* __restrict__ x,
    const float* __restrict__ wt,
    float* __restrict__ out)
{
    const int lane = threadIdx.x & 31;
    const int x0 = (int)threadIdx.x << 2;          // 0..1020
    const int b = blockIdx.x;
    const int y0 = (b & 63) << 4;                  // 64 16-row tiles
    const int nc = b >> 6;                         // 0..47
    const int c = nc % 3;

    const float* base = x + ((size_t)nc << 20) + x0;
    const bool interior = (y0 != 0) && (y0 != IMG_H - TROWS);

    // ---- tile-1 batch: 10 branch-free row loads (rows y0-1 .. y0+8) ----
    float4 vA[10];
    if (interior) {
#pragma unroll
        for (int i = 0; i < 10; i++)
            vA[i] = *reinterpret_cast<const float4*>(base + (size_t)(y0 - 1 + i) * IMG_W);
    } else {
#pragma unroll
        for (int i = 0; i < 10; i++) {
            const int rr = y0 - 1 + i;
            const int rc = min(IMG_H - 1, max(0, rr));
            vA[i] = *reinterpret_cast<const float4*>(base + (size_t)rc * IMG_W);
            if (rr != rc) vA[i] = make_float4(0.f, 0.f, 0.f, 0.f);
        }
    }

    // weights after bulk loads are in flight
    float w[9];
    float ws2 = 0.f;
#pragma unroll
    for (int k = 0; k < 9; k++) { w[k] = __ldg(&wt[c * 9 + k]); ws2 += w[k] * w[k]; }
    const float winv = rsqrtf(ws2);
#pragma unroll
    for (int k = 0; k < 9; k++) w[k] *= winv;

    float4 vB[8];
    float num[8][4], sq[8][4];
    float* op = out + ((size_t)nc << 20) + (size_t)y0 * IMG_W + x0;

    // ================= tile 1 (outputs y0 .. y0+7) =================
    float h0c = __shfl_up_sync(0xffffffffu, vA[0].w, 1);
    float h5c = __shfl_down_sync(0xffffffffu, vA[0].x, 1);
    {
        const int rr = y0 - 1;
        if (lane == 0)  h0c = (x0 > 0 && rr >= 0)          ? __ldg(base + (size_t)rr * IMG_W - 1) : 0.f;
        if (lane == 31) h5c = (x0 + 4 < IMG_W && rr >= 0)  ? __ldg(base + (size_t)rr * IMG_W + 4) : 0.f;
    }

#pragma unroll
    for (int r = 0; r < 10; r++) {
        // issue tile-2 batch once vA[0..8] are dead
        if (r == 9) {
            if (interior) {
#pragma unroll
                for (int i = 0; i < 8; i++)
                    vB[i] = *reinterpret_cast<const float4*>(base + (size_t)(y0 + 9 + i) * IMG_W);
            } else {
#pragma unroll
                for (int i = 0; i < 8; i++) {
                    const int rr = y0 + 9 + i;
                    const int rc = min(IMG_H - 1, max(0, rr));
                    vB[i] = *reinterpret_cast<const float4*>(base + (size_t)rc * IMG_W);
                    if (rr != rc) vB[i] = make_float4(0.f, 0.f, 0.f, 0.f);
                }
            }
        }

        float h0n = 0.f, h5n = 0.f;
        if (r + 1 < 10) {
            h0n = __shfl_up_sync(0xffffffffu, vA[r + 1].w, 1);
            h5n = __shfl_down_sync(0xffffffffu, vA[r + 1].x, 1);
            const int rr = y0 + r;                 // global row of vA[r+1]
            if (lane == 0)  h0n = (x0 > 0 && rr < IMG_H)         ? __ldg(base + (size_t)rr * IMG_W - 1) : 0.f;
            if (lane == 31) h5n = (x0 + 4 < IMG_W && rr < IMG_H) ? __ldg(base + (size_t)rr * IMG_W + 4) : 0.f;
        }

        const float a[6] = { h0c, vA[r].x, vA[r].y, vA[r].z, vA[r].w, h5c };

        float p[6];
#pragma unroll
        for (int i = 0; i < 6; i++) p[i] = a[i] * a[i];
        const float u = p[1] + p[2];
        const float t = p[3] + p[4];
        const float s[4] = { p[0] + u, u + p[3], p[2] + t, t + p[5] };

#pragma unroll
        for (int o = 0; o < 8; o++) {
            const int k = r - o;
            if (k == 0) {
#pragma unroll
                for (int j = 0; j < 4; j++) {
                    num[o][j] = fmaf(w[0], a[j], fmaf(w[1], a[j + 1], w[2] * a[j + 2]));
                    sq[o][j] = s[j];
                }
            } else if (k == 1 || k == 2) {
                const float w0 = w[k * 3 + 0], w1 = w[k * 3 + 1], w2 = w[k * 3 + 2];
#pragma unroll
                for (int j = 0; j < 4; j++) {
                    num[o][j] = fmaf(w0, a[j], fmaf(w1, a[j + 1], fmaf(w2, a[j + 2], num[o][j])));
                    sq[o][j] += s[j];
                }
            }
        }

        if (r >= 2) {
            const int o = r - 2;
            float4 ov;
            ov.x = num[o][0] * rsqrtf(sq[o][0]);
            ov.y = num[o][1] * rsqrtf(sq[o][1]);
            ov.z = num[o][2] * rsqrtf(sq[o][2]);
            ov.w = num[o][3] * rsqrtf(sq[o][3]);
            *reinterpret_cast<float4*>(op + (size_t)o * IMG_W) = ov;
        }

        h0c = h0n; h5c = h5n;
    }

    // ================= tile 2 (outputs y0+8 .. y0+15) =================
    float* op2 = op + (size_t)8 * IMG_W;

    // prologue halo from vA[8] (global row y0+7, always in-image)
    h0c = __shfl_up_sync(0xffffffffu, vA[8].w, 1);
    h5c = __shfl_down_sync(0xffffffffu, vA[8].x, 1);
    {
        const int rr = y0 + 7;
        if (lane == 0)  h0c = (x0 > 0)          ? __ldg(base + (size_t)rr * IMG_W - 1) : 0.f;
        if (lane == 31) h5c = (x0 + 4 < IMG_W)  ? __ldg(base + (size_t)rr * IMG_W + 4) : 0.f;
    }

#pragma unroll
    for (int r = 0; r < 10; r++) {
        // static row source: in[0]=vA[8], in[1]=vA[9], in[r]=vB[r-2]
        const float4 vc = (r == 0) ? vA[8] : (r == 1) ? vA[9] : vB[(r >= 2) ? (r - 2) : 0];

        float h0n = 0.f, h5n = 0.f;
        if (r + 1 < 10) {
            const float4 vn = (r + 1 == 1) ? vA[9] : vB[(r + 1 >= 2) ? (r - 1) : 0];
            h0n = __shfl_up_sync(0xffffffffu, vn.w, 1);
            h5n = __shfl_down_sync(0xffffffffu, vn.x, 1);
            const int rr = y0 + 8 + r;             // global row of vn
            if (lane == 0)  h0n = (x0 > 0 && rr < IMG_H)         ? __ldg(base + (size_t)rr * IMG_W - 1) : 0.f;
            if (lane == 31) h5n = (x0 + 4 < IMG_W && rr < IMG_H) ? __ldg(base + (size_t)rr * IMG_W + 4) : 0.f;
        }

        const float a[6] = { h0c, vc.x, vc.y, vc.z, vc.w, h5c };

        float p[6];
#pragma unroll
        for (int i = 0; i < 6; i++) p[i] = a[i] * a[i];
        const float u = p[1] + p[2];
        const float t = p[3] + p[4];
        const float s[4] = { p[0] + u, u + p[3], p[2] + t, t + p[5] };

#pragma unroll
        for (int o = 0; o < 8; o++) {
            const int k = r - o;
            if (k == 0) {
#pragma unroll
                for (int j = 0; j < 4; j++) {
                    num[o][j] = fmaf(w[0], a[j], fmaf(w[1], a[j + 1], w[2] * a[j + 2]));
                    sq[o][j] = s[j];
                }
            } else if (k == 1 || k == 2) {
                const float w0 = w[k * 3 + 0], w1 = w[k * 3 + 1], w2 = w[k * 3 + 2];
#pragma unroll
                for (int j = 0; j < 4; j++) {
                    num[o][j] = fmaf(w0, a[j], fmaf(w1, a[j + 1], fmaf(w2, a[j + 2], num[o][j])));
                    sq[o][j] += s[j];
                }
            }
        }

        if (r >= 2) {
            const int o = r - 2;
            float4 ov;
            ov.x = num[o][0] * rsqrtf(sq[o][0]);
            ov.y = num[o][1] * rsqrtf(sq[o][1]);
            ov.z = num[o][2] * rsqrtf(sq[o][2]);
            ov.w = num[o][3] * rsqrtf(sq[o][3]);
            *reinterpret_cast<float4*>(op2 + (size_t)o * IMG_W) = ov;
        }

        h0c = h0n; h5c = h5n;
    }
}

extern "C" void kernel_launch(void* const* d_in, const int* in_sizes, int n_in,
                              void* d_out, int out_size) {
    const float* x  = (const float*)d_in[0];
    const float* wt = (const float*)d_in[1];
    float* out = (float*)d_out;

    dim3 grid(NC_TOTAL * (IMG_H / TROWS));   // 3072 blocks, 256 threads = full row width
    normconv3x3_v10<<<grid, 256>>>(x, wt, out);
}